// round 14
// baseline (speedup 1.0000x reference)
#include <cuda_runtime.h>
#include <cuda_fp16.h>
#include <cstdint>

#define CHARS   10000
#define HIDDEN  1024
#define OUTPUT  100
#define BATCH   4096
#define MAXLEN  2048

#define K_PAD   10240
#define PPITCH  104                   // g_part row pitch (halfs)
#define NSLICE  8
#define K_SLICE (K_PAD / NSLICE)      // 1280
#define NCHUNK_MAIN (K_SLICE / 64)    // 20
#define NCHUNK_WC   (HIDDEN / 64)     // 16

// ---------------- device scratch (static; allocations are banned) --------
__device__ __half  g_hist[(size_t)BATCH * K_PAD];           // 84 MB
__device__ __half  g_w2f[(size_t)128 * HIDDEN];             // 256 KB
__device__ __half  g_wcf[(size_t)128 * K_PAD];              // 2.6 MB
__device__ __half  g_part[(size_t)BATCH * NSLICE * PPITCH]; // 6.8 MB [b][sl][o]
__device__ __align__(16) float g_bc[OUTPUT];

// ---------------- PTX helpers (portable sm_80-class only) ----------------
__device__ __forceinline__ uint32_t smem_u32(const void* p) {
    uint32_t a;
    asm("{ .reg .u64 t; cvta.to.shared.u64 t, %1; cvt.u32.u64 %0, t; }"
        : "=r"(a) : "l"(p));
    return a;
}

__device__ __forceinline__ void cp16(uint32_t s, const void* g) {
    asm volatile("cp.async.cg.shared.global [%0], [%1], 16;" :: "r"(s), "l"(g));
}
__device__ __forceinline__ void cp16ca(uint32_t s, const void* g) {
    asm volatile("cp.async.ca.shared.global [%0], [%1], 16;" :: "r"(s), "l"(g));
}
#define CP_COMMIT() asm volatile("cp.async.commit_group;" ::: "memory")
#define CP_WAIT1()  asm volatile("cp.async.wait_group 1;"  ::: "memory")

__device__ __forceinline__ void ldsm4(uint32_t* r, uint32_t a) {
    asm volatile("ldmatrix.sync.aligned.m8n8.x4.shared.b16 {%0,%1,%2,%3}, [%4];"
        : "=r"(r[0]), "=r"(r[1]), "=r"(r[2]), "=r"(r[3]) : "r"(a));
}
__device__ __forceinline__ void ldsm4t(uint32_t* r, uint32_t a) {
    asm volatile("ldmatrix.sync.aligned.m8n8.x4.trans.shared.b16 {%0,%1,%2,%3}, [%4];"
        : "=r"(r[0]), "=r"(r[1]), "=r"(r[2]), "=r"(r[3]) : "r"(a));
}

// D(16x8,f32) += A(16x16,f16) @ B(16x8,f16)
__device__ __forceinline__ void mma_f16(float* c, const uint32_t* a, const uint32_t* b) {
    asm volatile(
        "mma.sync.aligned.m16n8k16.row.col.f32.f16.f16.f32 "
        "{%0,%1,%2,%3}, {%4,%5,%6,%7}, {%8,%9}, {%0,%1,%2,%3};"
        : "+f"(c[0]), "+f"(c[1]), "+f"(c[2]), "+f"(c[3])
        : "r"(a[0]), "r"(a[1]), "r"(a[2]), "r"(a[3]), "r"(b[0]), "r"(b[1]));
}

#define PA 144     // smem pitch (bytes) for 64-col 16-bit rows, +8 elem pad

// ---------------- kernel 1: conv (W2 -> fp16) + bc  (3 us, runs first) ---
#define NB_W2 512
#define NB_BC 13
#define NB_CONV (NB_W2 + NB_BC)

__global__ void __launch_bounds__(256) conv_kernel(
        const float* __restrict__ b1, const float* __restrict__ W2,
        const float* __restrict__ b2) {
    const int bid = blockIdx.x, tid = threadIdx.x;
    if (bid < NB_W2) {
        unsigned i = bid * 256u + tid;                 // over 128*1024
        unsigned o = i >> 10;
        float v = (o < OUTPUT) ? W2[(size_t)o * HIDDEN + (i & 1023u)] : 0.f;
        g_w2f[i] = __float2half_rn(v);
    } else {
        int o = (bid - NB_W2) * 8 + (tid >> 5);
        if (o < OUTPUT) {
            int lane = tid & 31;
            const float* w = W2 + (size_t)o * HIDDEN;
            float s = 0.f;
            #pragma unroll 8
            for (int h = lane; h < HIDDEN; h += 32) s += w[h] * b1[h];
            #pragma unroll
            for (int off = 16; off; off >>= 1)
                s += __shfl_xor_sync(0xFFFFFFFFu, s, off);
            if (lane == 0) g_bc[o] = b2[o] + s;
        }
    }
}

// ---------------- kernel 2a: histogram (stream 0, 4096 blocks) -----------
__global__ void __launch_bounds__(256) hist_kernel(const int* __restrict__ words) {
    __shared__ __align__(16) unsigned cnt[K_PAD / 2];
    const int bid = blockIdx.x, tid = threadIdx.x;
    uint4 z = make_uint4(0u, 0u, 0u, 0u);
    uint4* cz = (uint4*)cnt;
    #pragma unroll
    for (int i = tid; i < K_PAD / 8; i += 256) cz[i] = z;
    __syncthreads();
    const int* w = words + (size_t)bid * MAXLEN;
    #pragma unroll 8
    for (int j = tid; j < MAXLEN; j += 256) {
        unsigned c = (unsigned)w[j];
        atomicAdd(&cnt[c >> 1], 1u << ((c & 1u) * 16));
    }
    __syncthreads();
    uint4* out = (uint4*)(g_hist + (size_t)bid * K_PAD);
    #pragma unroll
    for (int i = tid; i < K_PAD / 8; i += 256) {
        unsigned c0 = cnt[4 * i], c1 = cnt[4 * i + 1];
        unsigned c2 = cnt[4 * i + 2], c3 = cnt[4 * i + 3];
        __half2 h0 = __floats2half2_rn((float)(c0 & 0xFFFFu), (float)(c0 >> 16));
        __half2 h1 = __floats2half2_rn((float)(c1 & 0xFFFFu), (float)(c1 >> 16));
        __half2 h2 = __floats2half2_rn((float)(c2 & 0xFFFFu), (float)(c2 >> 16));
        __half2 h3 = __floats2half2_rn((float)(c3 & 0xFFFFu), (float)(c3 >> 16));
        out[i] = make_uint4(*(uint32_t*)&h0, *(uint32_t*)&h1,
                            *(uint32_t*)&h2, *(uint32_t*)&h3);
    }
}

// ---------------- kernel 2b: Wc = W2 @ W1 (high-priority stream) ---------
// CTA 128 o x 64 c, K=1024 (16 chunks). grid 160. 8 warps (4m x 2n).
#define WC_A 0
#define WC_B 18432
#define WC_STG 27648

__global__ void __launch_bounds__(256, 2) wc_gemm(const float* __restrict__ W1) {
    extern __shared__ char smn[];
    uint32_t sb = smem_u32(smn);
    const int tid = threadIdx.x, lid = tid & 31, wid = tid >> 5;
    const int wm = wid >> 1, wn = wid & 1, gid = lid >> 2, t4 = lid & 3;
    const int c0 = blockIdx.x * 64;

    const int arow = tid >> 1;
    const int acol = (tid & 1) * 64;
    const char* gA = (const char*)(g_w2f + (size_t)arow * HIDDEN) + acol;
    const uint32_t sA = sb + WC_A + arow * PA + acol;

    const int brow = tid >> 2;
    const int bcole = (tid & 3) * 16;
    const uint32_t oB = WC_B + brow * PA + bcole * 2;

    float4 rb[4];
    auto loadB = [&](int it) {
        const float* p = W1 + (size_t)(it * 64 + brow) * CHARS + c0 + bcole;
        #pragma unroll
        for (int i = 0; i < 4; i++) {
            int c = c0 + bcole + i * 4;
            rb[i] = (c < CHARS) ? *(const float4*)(p + i * 4)
                                : make_float4(0.f, 0.f, 0.f, 0.f);
        }
    };
    auto stsB = [&](int slot) {
        uint32_t so = slot * WC_STG;
        #pragma unroll
        for (int j = 0; j < 2; j++) {
            __half2 h0 = __floats2half2_rn(rb[2*j].x,   rb[2*j].y);
            __half2 h1 = __floats2half2_rn(rb[2*j].z,   rb[2*j].w);
            __half2 h2 = __floats2half2_rn(rb[2*j+1].x, rb[2*j+1].y);
            __half2 h3 = __floats2half2_rn(rb[2*j+1].z, rb[2*j+1].w);
            *(uint4*)(smn + oB + so + j * 16) =
                make_uint4(*(uint32_t*)&h0, *(uint32_t*)&h1,
                           *(uint32_t*)&h2, *(uint32_t*)&h3);
        }
    };
    auto cpA = [&](int it, int slot) {
        if (it < NCHUNK_WC) {
            uint32_t so = slot * WC_STG;
            size_t ka = (size_t)it * 128;
            #pragma unroll
            for (int i = 0; i < 4; i++) cp16(sA + so + i * 16, gA + ka + i * 16);
        }
        CP_COMMIT();
    };

    float acc[2][4][4];
    #pragma unroll
    for (int mb = 0; mb < 2; mb++)
        #pragma unroll
        for (int nf = 0; nf < 4; nf++)
            #pragma unroll
            for (int e = 0; e < 4; e++) acc[mb][nf][e] = 0.f;

    loadB(0); stsB(0);
    loadB(1);
    cpA(0, 0); cpA(1, 1);

    int sc = 0, sn = 2;
    for (int it = 0; it < NCHUNK_WC; ++it) {
        uint32_t st = sb + sc * WC_STG;
        CP_WAIT1();
        __syncthreads();
        if (it + 1 < NCHUNK_WC) stsB((it + 1) % 3);
        if (it + 2 < NCHUNK_WC) loadB(it + 2);
        cpA(it + 2, sn);
        #pragma unroll
        for (int ks = 0; ks < 4; ks++) {
            uint32_t a[2][4];
            #pragma unroll
            for (int mb = 0; mb < 2; mb++) {
                uint32_t r = (wm * 32 + mb * 16 + (lid & 15));
                ldsm4(a[mb], st + WC_A + r * PA + ks * 32 + (lid >> 4) * 16);
            }
            #pragma unroll
            for (int nq = 0; nq < 2; nq++) {
                uint32_t r = ks * 16 + ((lid >> 3) & 1) * 8 + (lid & 7);
                uint32_t cb = (wn * 32 + nq * 16) * 2 + ((lid >> 4) & 1) * 16;
                uint32_t b[4];
                ldsm4t(b, st + WC_B + r * PA + cb);
                #pragma unroll
                for (int mb = 0; mb < 2; mb++)
                    #pragma unroll
                    for (int f = 0; f < 2; f++)
                        mma_f16(acc[mb][nq * 2 + f], a[mb], &b[f * 2]);
            }
        }
        sc = (sc == 2) ? 0 : sc + 1;
        sn = (sn == 2) ? 0 : sn + 1;
    }

    #pragma unroll
    for (int mb = 0; mb < 2; mb++)
        #pragma unroll
        for (int nf = 0; nf < 4; nf++) {
            int o = wm * 32 + mb * 16 + gid;
            int c = c0 + wn * 32 + nf * 8 + t4 * 2;
            *(__half2*)(g_wcf + (size_t)o * K_PAD + c) =
                __floats2half2_rn(acc[mb][nf][0], acc[mb][nf][1]);
            *(__half2*)(g_wcf + (size_t)(o + 8) * K_PAD + c) =
                __floats2half2_rn(acc[mb][nf][2], acc[mb][nf][3]);
        }
}

// ---------------- kernel 3: main GEMM  part = hist @ Wc^T (fp16) ---------
// CTA 128 m x 112 n (covers OUTPUT=100), 128 threads = 4 warps.
// wn=0 warps: 64x64; wn=1 warps: 64x48. 3 stages, 1 barrier/iter.
// Partials stored as fp16 (halves store + reduce traffic).
#define MG_A    0                      // 3 x 18432
#define MG_B    55296                  // 3 x 16128
#define B_STG   16128                  // 112 * 144
#define MG_SMEM (55296 + 3 * B_STG)    // 103680

__global__ void __launch_bounds__(128, 2) main_gemm() {
    extern __shared__ char smn[];
    uint32_t sb = smem_u32(smn);
    const int tid = threadIdx.x, lid = tid & 31, wid = tid >> 5;
    const int wm = wid >> 1, wn = wid & 1, gid = lid >> 2, t4 = lid & 3;
    const int m0 = blockIdx.x * 128;
    const int kbase = blockIdx.y * K_SLICE;
    const int nqmax = 4 - wn;

    const char* gA = (const char*)(g_hist + (size_t)(m0 + tid) * K_PAD + kbase);
    const uint32_t sA = sb + MG_A + tid * PA;
    const int rb8  = tid >> 3;
    const int bcol = (tid & 7) * 16;
    const char* gBc = (const char*)g_wcf + (size_t)kbase * 2 + bcol;
    const uint32_t sBb = sb + MG_B + bcol;

    auto issue = [&](int it, int s) {
        if (it < NCHUNK_MAIN) {
            size_t ko = (size_t)it * 128;
            uint32_t soA = s * 18432, soB = s * B_STG;
            #pragma unroll
            for (int i = 0; i < 8; i++)
                cp16(sA + soA + i * 16, gA + ko + i * 16);
            #pragma unroll
            for (int i = 0; i < 7; i++) {
                int row = i * 16 + rb8;
                cp16ca(sBb + soB + row * PA,
                       gBc + (size_t)row * (K_PAD * 2) + ko);
            }
        }
        CP_COMMIT();
    };

    float acc[4][8][4];
    #pragma unroll
    for (int mb = 0; mb < 4; mb++)
        #pragma unroll
        for (int nf = 0; nf < 8; nf++)
            #pragma unroll
            for (int e = 0; e < 4; e++) acc[mb][nf][e] = 0.f;

    const uint32_t aoff = (wm * 64 + (lid & 15)) * PA + (lid >> 4) * 16;
    const uint32_t boff = (wn * 64 + ((lid >> 4) & 1) * 8 + (lid & 7)) * PA
                          + ((lid >> 3) & 1) * 16;

    issue(0, 0); issue(1, 1);
    int sc = 0, sn = 2;
    for (int it = 0; it < NCHUNK_MAIN; ++it) {
        uint32_t stA = sb + MG_A + sc * 18432;
        uint32_t stB = sb + MG_B + sc * B_STG;
        CP_WAIT1();
        __syncthreads();
        issue(it + 2, sn);
        #pragma unroll
        for (int ks = 0; ks < 4; ks++) {
            uint32_t ko = ks * 32;
            uint32_t a[4][4], b[4][4];
            #pragma unroll
            for (int mb = 0; mb < 4; mb++)
                ldsm4(a[mb], stA + aoff + mb * 16 * PA + ko);
            #pragma unroll
            for (int nq = 0; nq < 4; nq++)
                if (nq < nqmax)
                    ldsm4(b[nq], stB + boff + nq * 16 * PA + ko);
            #pragma unroll
            for (int nq = 0; nq < 4; nq++)
                if (nq < nqmax)
                    #pragma unroll
                    for (int mb = 0; mb < 4; mb++)
                        #pragma unroll
                        for (int f = 0; f < 2; f++)
                            mma_f16(acc[mb][nq * 2 + f], a[mb], &b[nq][f * 2]);
        }
        sc = (sc == 2) ? 0 : sc + 1;
        sn = (sn == 2) ? 0 : sn + 1;
    }

    // epilogue: fp16 partials, layout [b][sl][PPITCH]
    #pragma unroll
    for (int mb = 0; mb < 4; mb++)
        #pragma unroll
        for (int nf = 0; nf < 8; nf++) {
            int r = m0 + wm * 64 + mb * 16 + gid;
            int c = wn * 64 + nf * 8 + t4 * 2;
            if (c < OUTPUT) {
                *(__half2*)(g_part + ((size_t)r * NSLICE + blockIdx.y) * PPITCH + c) =
                    __floats2half2_rn(acc[mb][nf][0], acc[mb][nf][1]);
                *(__half2*)(g_part + ((size_t)(r + 8) * NSLICE + blockIdx.y) * PPITCH + c) =
                    __floats2half2_rn(acc[mb][nf][2], acc[mb][nf][3]);
            }
        }
}

// ---------------- kernel 4: split-K reduce + bias (fp16 partials) --------
__global__ void __launch_bounds__(256) reduce_kernel(float* __restrict__ out) {
    int w = threadIdx.x >> 5, lane = threadIdx.x & 31;
    int b = blockIdx.x * 8 + w;
    if (lane < 25) {
        int o = lane * 4;
        float4 s = *(const float4*)(g_bc + o);
        const __half* pb = g_part + (size_t)b * NSLICE * PPITCH + o;
        #pragma unroll
        for (int sl = 0; sl < NSLICE; sl++) {
            uint2 v = *(const uint2*)(pb + sl * PPITCH);
            float2 p0 = __half22float2(*(__half2*)&v.x);
            float2 p1 = __half22float2(*(__half2*)&v.y);
            s.x += p0.x; s.y += p0.y; s.z += p1.x; s.w += p1.y;
        }
        *(float4*)(out + (size_t)b * OUTPUT + o) = s;
    }
}

// ---------------- launch ---------------------------------------------------
extern "C" void kernel_launch(void* const* d_in, const int* in_sizes, int n_in,
                              void* d_out, int out_size) {
    const int*   words = (const int*)  d_in[0];
    const float* W1    = (const float*)d_in[1];
    const float* b1    = (const float*)d_in[2];
    const float* W2    = (const float*)d_in[3];
    const float* b2    = (const float*)d_in[4];

    // high-priority side stream so wc CTAs get SM slots WHILE hist's 4096
    // blocks occupy the chip (plain fork in R7 just queued behind them).
    static cudaStream_t s2 = nullptr;
    static cudaEvent_t ev_fork = nullptr, ev_join = nullptr;
    if (s2 == nullptr) {
        int plo, phi;
        cudaDeviceGetStreamPriorityRange(&plo, &phi);
        cudaStreamCreateWithPriority(&s2, cudaStreamNonBlocking, phi);
        cudaEventCreateWithFlags(&ev_fork, cudaEventDisableTiming);
        cudaEventCreateWithFlags(&ev_join, cudaEventDisableTiming);
        cudaFuncSetAttribute(wc_gemm,
            cudaFuncAttributeMaxDynamicSharedMemorySize, 3 * WC_STG);
        cudaFuncSetAttribute(main_gemm,
            cudaFuncAttributeMaxDynamicSharedMemorySize, MG_SMEM);
    }

    conv_kernel<<<NB_CONV, 256, 0, 0>>>(b1, W2, b2);

    cudaEventRecord(ev_fork, 0);
    cudaStreamWaitEvent(s2, ev_fork, 0);

    hist_kernel<<<BATCH, 256, 0, 0>>>(words);                 // stream 0
    wc_gemm<<<K_PAD / 64, 256, 3 * WC_STG, s2>>>(W1);         // high prio
    cudaEventRecord(ev_join, s2);

    cudaStreamWaitEvent(0, ev_join, 0);
    main_gemm<<<dim3(32, NSLICE), 128, MG_SMEM, 0>>>();
    reduce_kernel<<<BATCH / 8, 256, 0, 0>>>((float*)d_out);
}

// round 15
// speedup vs baseline: 1.0301x; 1.0301x over previous
#include <cuda_runtime.h>
#include <cuda_fp16.h>
#include <cstdint>

#define CHARS   10000
#define HIDDEN  1024
#define OUTPUT  100
#define BATCH   4096
#define MAXLEN  2048

#define K_PAD   10240
#define PPITCH  104                   // g_part row pitch (halfs)
#define NSLICE  8
#define K_SLICE (K_PAD / NSLICE)      // 1280
#define NCHUNK_MAIN (K_SLICE / 64)    // 20
#define NCHUNK_WC   (HIDDEN / 64)     // 16

// ---------------- device scratch (static; allocations are banned) --------
__device__ __half  g_hist[(size_t)BATCH * K_PAD];           // 84 MB
__device__ __half  g_w2f[(size_t)128 * HIDDEN];             // 256 KB
__device__ __half  g_wcf[(size_t)128 * K_PAD];              // 2.6 MB
__device__ __half  g_part[(size_t)BATCH * NSLICE * PPITCH]; // 6.8 MB [b][sl][o]
__device__ __align__(16) float g_bc[OUTPUT];

// ---------------- PTX helpers (portable sm_80-class only) ----------------
__device__ __forceinline__ uint32_t smem_u32(const void* p) {
    uint32_t a;
    asm("{ .reg .u64 t; cvta.to.shared.u64 t, %1; cvt.u32.u64 %0, t; }"
        : "=r"(a) : "l"(p));
    return a;
}

__device__ __forceinline__ void cp16(uint32_t s, const void* g) {
    asm volatile("cp.async.cg.shared.global [%0], [%1], 16;" :: "r"(s), "l"(g));
}
__device__ __forceinline__ void cp16ca(uint32_t s, const void* g) {
    asm volatile("cp.async.ca.shared.global [%0], [%1], 16;" :: "r"(s), "l"(g));
}
#define CP_COMMIT() asm volatile("cp.async.commit_group;" ::: "memory")
#define CP_WAIT1()  asm volatile("cp.async.wait_group 1;"  ::: "memory")

__device__ __forceinline__ void ldsm4(uint32_t* r, uint32_t a) {
    asm volatile("ldmatrix.sync.aligned.m8n8.x4.shared.b16 {%0,%1,%2,%3}, [%4];"
        : "=r"(r[0]), "=r"(r[1]), "=r"(r[2]), "=r"(r[3]) : "r"(a));
}
__device__ __forceinline__ void ldsm4t(uint32_t* r, uint32_t a) {
    asm volatile("ldmatrix.sync.aligned.m8n8.x4.trans.shared.b16 {%0,%1,%2,%3}, [%4];"
        : "=r"(r[0]), "=r"(r[1]), "=r"(r[2]), "=r"(r[3]) : "r"(a));
}

// D(16x8,f32) += A(16x16,f16) @ B(16x8,f16)
__device__ __forceinline__ void mma_f16(float* c, const uint32_t* a, const uint32_t* b) {
    asm volatile(
        "mma.sync.aligned.m16n8k16.row.col.f32.f16.f16.f32 "
        "{%0,%1,%2,%3}, {%4,%5,%6,%7}, {%8,%9}, {%0,%1,%2,%3};"
        : "+f"(c[0]), "+f"(c[1]), "+f"(c[2]), "+f"(c[3])
        : "r"(a[0]), "r"(a[1]), "r"(a[2]), "r"(a[3]), "r"(b[0]), "r"(b[1]));
}

#define PA 144     // smem pitch (bytes) for 64-col 16-bit rows, +8 elem pad

// ---------------- kernel 1: prelude (hist + W2 conv + bc) ----------------
#define NB_HIST 4096
#define NB_W2   512
#define NB_BC   13
#define NB_TOTAL (NB_HIST + NB_W2 + NB_BC)

__global__ void __launch_bounds__(256) prelude_kernel(
        const int* __restrict__ words, const float* __restrict__ b1,
        const float* __restrict__ W2,  const float* __restrict__ b2) {
    __shared__ __align__(16) unsigned cnt[K_PAD / 2];
    const int bid = blockIdx.x, tid = threadIdx.x;

    if (bid < NB_HIST) {
        uint4 z = make_uint4(0u, 0u, 0u, 0u);
        uint4* cz = (uint4*)cnt;
        #pragma unroll
        for (int i = tid; i < K_PAD / 8; i += 256) cz[i] = z;
        __syncthreads();
        const int* w = words + (size_t)bid * MAXLEN;
        #pragma unroll 8
        for (int j = tid; j < MAXLEN; j += 256) {
            unsigned c = (unsigned)w[j];
            atomicAdd(&cnt[c >> 1], 1u << ((c & 1u) * 16));
        }
        __syncthreads();
        uint4* out = (uint4*)(g_hist + (size_t)bid * K_PAD);
        #pragma unroll
        for (int i = tid; i < K_PAD / 8; i += 256) {
            unsigned c0 = cnt[4 * i], c1 = cnt[4 * i + 1];
            unsigned c2 = cnt[4 * i + 2], c3 = cnt[4 * i + 3];
            __half2 h0 = __floats2half2_rn((float)(c0 & 0xFFFFu), (float)(c0 >> 16));
            __half2 h1 = __floats2half2_rn((float)(c1 & 0xFFFFu), (float)(c1 >> 16));
            __half2 h2 = __floats2half2_rn((float)(c2 & 0xFFFFu), (float)(c2 >> 16));
            __half2 h3 = __floats2half2_rn((float)(c3 & 0xFFFFu), (float)(c3 >> 16));
            out[i] = make_uint4(*(uint32_t*)&h0, *(uint32_t*)&h1,
                                *(uint32_t*)&h2, *(uint32_t*)&h3);
        }
    } else if (bid < NB_HIST + NB_W2) {
        unsigned i = (bid - NB_HIST) * 256u + tid;           // over 128*1024
        unsigned o = i >> 10;
        float v = (o < OUTPUT) ? W2[(size_t)o * HIDDEN + (i & 1023u)] : 0.f;
        g_w2f[i] = __float2half_rn(v);
    } else {
        int o = (bid - NB_HIST - NB_W2) * 8 + (tid >> 5);
        if (o < OUTPUT) {
            int lane = tid & 31;
            const float* w = W2 + (size_t)o * HIDDEN;
            float s = 0.f;
            #pragma unroll 8
            for (int h = lane; h < HIDDEN; h += 32) s += w[h] * b1[h];
            #pragma unroll
            for (int off = 16; off; off >>= 1)
                s += __shfl_xor_sync(0xFFFFFFFFu, s, off);
            if (lane == 0) g_bc[o] = b2[o] + s;
        }
    }
}

// ---------------- kernel 2: Wc = W2 @ W1 (fused W1 fp32->fp16) -----------
// CTA 128 o x 64 c, K=1024 (16 chunks). grid 160. 8 warps (4m x 2n).
#define WC_A 0
#define WC_B 18432
#define WC_STG 27648

__global__ void __launch_bounds__(256, 2) wc_gemm(const float* __restrict__ W1) {
    extern __shared__ char smn[];
    uint32_t sb = smem_u32(smn);
    const int tid = threadIdx.x, lid = tid & 31, wid = tid >> 5;
    const int wm = wid >> 1, wn = wid & 1, gid = lid >> 2, t4 = lid & 3;
    const int c0 = blockIdx.x * 64;

    const int arow = tid >> 1;
    const int acol = (tid & 1) * 64;
    const char* gA = (const char*)(g_w2f + (size_t)arow * HIDDEN) + acol;
    const uint32_t sA = sb + WC_A + arow * PA + acol;

    const int brow = tid >> 2;
    const int bcole = (tid & 3) * 16;
    const uint32_t oB = WC_B + brow * PA + bcole * 2;

    float4 rb[4];
    auto loadB = [&](int it) {
        const float* p = W1 + (size_t)(it * 64 + brow) * CHARS + c0 + bcole;
        #pragma unroll
        for (int i = 0; i < 4; i++) {
            int c = c0 + bcole + i * 4;
            rb[i] = (c < CHARS) ? *(const float4*)(p + i * 4)
                                : make_float4(0.f, 0.f, 0.f, 0.f);
        }
    };
    auto stsB = [&](int slot) {
        uint32_t so = slot * WC_STG;
        #pragma unroll
        for (int j = 0; j < 2; j++) {
            __half2 h0 = __floats2half2_rn(rb[2*j].x,   rb[2*j].y);
            __half2 h1 = __floats2half2_rn(rb[2*j].z,   rb[2*j].w);
            __half2 h2 = __floats2half2_rn(rb[2*j+1].x, rb[2*j+1].y);
            __half2 h3 = __floats2half2_rn(rb[2*j+1].z, rb[2*j+1].w);
            *(uint4*)(smn + oB + so + j * 16) =
                make_uint4(*(uint32_t*)&h0, *(uint32_t*)&h1,
                           *(uint32_t*)&h2, *(uint32_t*)&h3);
        }
    };
    auto cpA = [&](int it, int slot) {
        if (it < NCHUNK_WC) {
            uint32_t so = slot * WC_STG;
            size_t ka = (size_t)it * 128;
            #pragma unroll
            for (int i = 0; i < 4; i++) cp16(sA + so + i * 16, gA + ka + i * 16);
        }
        CP_COMMIT();
    };

    float acc[2][4][4];
    #pragma unroll
    for (int mb = 0; mb < 2; mb++)
        #pragma unroll
        for (int nf = 0; nf < 4; nf++)
            #pragma unroll
            for (int e = 0; e < 4; e++) acc[mb][nf][e] = 0.f;

    loadB(0); stsB(0);
    loadB(1);
    cpA(0, 0); cpA(1, 1);

    int sc = 0, sn = 2;
    for (int it = 0; it < NCHUNK_WC; ++it) {
        uint32_t st = sb + sc * WC_STG;
        CP_WAIT1();
        __syncthreads();
        if (it + 1 < NCHUNK_WC) stsB((it + 1) % 3);
        if (it + 2 < NCHUNK_WC) loadB(it + 2);
        cpA(it + 2, sn);
        #pragma unroll
        for (int ks = 0; ks < 4; ks++) {
            uint32_t a[2][4];
            #pragma unroll
            for (int mb = 0; mb < 2; mb++) {
                uint32_t r = (wm * 32 + mb * 16 + (lid & 15));
                ldsm4(a[mb], st + WC_A + r * PA + ks * 32 + (lid >> 4) * 16);
            }
            #pragma unroll
            for (int nq = 0; nq < 2; nq++) {
                uint32_t r = ks * 16 + ((lid >> 3) & 1) * 8 + (lid & 7);
                uint32_t cb = (wn * 32 + nq * 16) * 2 + ((lid >> 4) & 1) * 16;
                uint32_t b[4];
                ldsm4t(b, st + WC_B + r * PA + cb);
                #pragma unroll
                for (int mb = 0; mb < 2; mb++)
                    #pragma unroll
                    for (int f = 0; f < 2; f++)
                        mma_f16(acc[mb][nq * 2 + f], a[mb], &b[f * 2]);
            }
        }
        sc = (sc == 2) ? 0 : sc + 1;
        sn = (sn == 2) ? 0 : sn + 1;
    }

    #pragma unroll
    for (int mb = 0; mb < 2; mb++)
        #pragma unroll
        for (int nf = 0; nf < 4; nf++) {
            int o = wm * 32 + mb * 16 + gid;
            int c = c0 + wn * 32 + nf * 8 + t4 * 2;
            *(__half2*)(g_wcf + (size_t)o * K_PAD + c) =
                __floats2half2_rn(acc[mb][nf][0], acc[mb][nf][1]);
            *(__half2*)(g_wcf + (size_t)(o + 8) * K_PAD + c) =
                __floats2half2_rn(acc[mb][nf][2], acc[mb][nf][3]);
        }
}

// ---------------- kernel 3: main GEMM  part = hist @ Wc^T (fp16) ---------
// CTA 128 m x 112 n (covers OUTPUT=100), 128 threads = 4 warps.
// wn=0 warps: 64x64; wn=1 warps: 64x48. 3 stages, 1 barrier/iter.
// Partials stored fp16 to [b][sl][PPITCH].
#define MG_A    0                      // 3 x 18432
#define MG_B    55296                  // 3 x 16128
#define B_STG   16128                  // 112 * 144
#define MG_SMEM (55296 + 3 * B_STG)    // 103680

__global__ void __launch_bounds__(128, 2) main_gemm() {
    extern __shared__ char smn[];
    uint32_t sb = smem_u32(smn);
    const int tid = threadIdx.x, lid = tid & 31, wid = tid >> 5;
    const int wm = wid >> 1, wn = wid & 1, gid = lid >> 2, t4 = lid & 3;
    const int m0 = blockIdx.x * 128;
    const int kbase = blockIdx.y * K_SLICE;
    const int nqmax = 4 - wn;

    const char* gA = (const char*)(g_hist + (size_t)(m0 + tid) * K_PAD + kbase);
    const uint32_t sA = sb + MG_A + tid * PA;
    const int rb8  = tid >> 3;
    const int bcol = (tid & 7) * 16;
    const char* gBc = (const char*)g_wcf + (size_t)kbase * 2 + bcol;
    const uint32_t sBb = sb + MG_B + bcol;

    auto issue = [&](int it, int s) {
        if (it < NCHUNK_MAIN) {
            size_t ko = (size_t)it * 128;
            uint32_t soA = s * 18432, soB = s * B_STG;
            #pragma unroll
            for (int i = 0; i < 8; i++)
                cp16(sA + soA + i * 16, gA + ko + i * 16);
            #pragma unroll
            for (int i = 0; i < 7; i++) {
                int row = i * 16 + rb8;
                cp16ca(sBb + soB + row * PA,
                       gBc + (size_t)row * (K_PAD * 2) + ko);
            }
        }
        CP_COMMIT();
    };

    float acc[4][8][4];
    #pragma unroll
    for (int mb = 0; mb < 4; mb++)
        #pragma unroll
        for (int nf = 0; nf < 8; nf++)
            #pragma unroll
            for (int e = 0; e < 4; e++) acc[mb][nf][e] = 0.f;

    const uint32_t aoff = (wm * 64 + (lid & 15)) * PA + (lid >> 4) * 16;
    const uint32_t boff = (wn * 64 + ((lid >> 4) & 1) * 8 + (lid & 7)) * PA
                          + ((lid >> 3) & 1) * 16;

    issue(0, 0); issue(1, 1);
    int sc = 0, sn = 2;
    for (int it = 0; it < NCHUNK_MAIN; ++it) {
        uint32_t stA = sb + MG_A + sc * 18432;
        uint32_t stB = sb + MG_B + sc * B_STG;
        CP_WAIT1();
        __syncthreads();
        issue(it + 2, sn);
        #pragma unroll
        for (int ks = 0; ks < 4; ks++) {
            uint32_t ko = ks * 32;
            uint32_t a[4][4], b[4][4];
            #pragma unroll
            for (int mb = 0; mb < 4; mb++)
                ldsm4(a[mb], stA + aoff + mb * 16 * PA + ko);
            #pragma unroll
            for (int nq = 0; nq < 4; nq++)
                if (nq < nqmax)
                    ldsm4(b[nq], stB + boff + nq * 16 * PA + ko);
            #pragma unroll
            for (int nq = 0; nq < 4; nq++)
                if (nq < nqmax)
                    #pragma unroll
                    for (int mb = 0; mb < 4; mb++)
                        #pragma unroll
                        for (int f = 0; f < 2; f++)
                            mma_f16(acc[mb][nq * 2 + f], a[mb], &b[nq][f * 2]);
        }
        sc = (sc == 2) ? 0 : sc + 1;
        sn = (sn == 2) ? 0 : sn + 1;
    }

    // epilogue: fp16 partials, layout [b][sl][PPITCH]
    #pragma unroll
    for (int mb = 0; mb < 4; mb++)
        #pragma unroll
        for (int nf = 0; nf < 8; nf++) {
            int r = m0 + wm * 64 + mb * 16 + gid;
            int c = wn * 64 + nf * 8 + t4 * 2;
            if (c < OUTPUT) {
                *(__half2*)(g_part + ((size_t)r * NSLICE + blockIdx.y) * PPITCH + c) =
                    __floats2half2_rn(acc[mb][nf][0], acc[mb][nf][1]);
                *(__half2*)(g_part + ((size_t)(r + 8) * NSLICE + blockIdx.y) * PPITCH + c) =
                    __floats2half2_rn(acc[mb][nf][2], acc[mb][nf][3]);
            }
        }
}

// ---------------- kernel 4: split-K reduce + bias (fp16 partials) --------
__global__ void __launch_bounds__(256) reduce_kernel(float* __restrict__ out) {
    int w = threadIdx.x >> 5, lane = threadIdx.x & 31;
    int b = blockIdx.x * 8 + w;
    if (lane < 25) {
        int o = lane * 4;
        float4 s = *(const float4*)(g_bc + o);
        const __half* pb = g_part + (size_t)b * NSLICE * PPITCH + o;
        #pragma unroll
        for (int sl = 0; sl < NSLICE; sl++) {
            uint2 v = *(const uint2*)(pb + sl * PPITCH);
            float2 p0 = __half22float2(*(__half2*)&v.x);
            float2 p1 = __half22float2(*(__half2*)&v.y);
            s.x += p0.x; s.y += p0.y; s.z += p1.x; s.w += p1.y;
        }
        *(float4*)(out + (size_t)b * OUTPUT + o) = s;
    }
}

// ---------------- launch ---------------------------------------------------
extern "C" void kernel_launch(void* const* d_in, const int* in_sizes, int n_in,
                              void* d_out, int out_size) {
    const int*   words = (const int*)  d_in[0];
    const float* W1    = (const float*)d_in[1];
    const float* b1    = (const float*)d_in[2];
    const float* W2    = (const float*)d_in[3];
    const float* b2    = (const float*)d_in[4];

    cudaFuncSetAttribute(wc_gemm,
        cudaFuncAttributeMaxDynamicSharedMemorySize, 3 * WC_STG);
    cudaFuncSetAttribute(main_gemm,
        cudaFuncAttributeMaxDynamicSharedMemorySize, MG_SMEM);

    prelude_kernel<<<NB_TOTAL, 256>>>(words, b1, W2, b2);
    wc_gemm<<<K_PAD / 64, 256, 3 * WC_STG>>>(W1);
    main_gemm<<<dim3(32, NSLICE), 128, MG_SMEM>>>();
    reduce_kernel<<<BATCH / 8, 256>>>((float*)d_out);
}

// round 16
// speedup vs baseline: 1.0420x; 1.0115x over previous
#include <cuda_runtime.h>
#include <cuda_fp16.h>
#include <cstdint>

#define CHARS   10000
#define HIDDEN  1024
#define OUTPUT  100
#define BATCH   4096
#define MAXLEN  2048

#define K_PAD   10240
#define PPITCH  104                   // g_part row pitch (halfs)
#define NSLICE  8
#define K_SLICE (K_PAD / NSLICE)      // 1280
#define NCHUNK_MAIN (K_SLICE / 64)    // 20
#define NCHUNK_WC   (HIDDEN / 64)     // 16

// ---------------- device scratch (static; allocations are banned) --------
__device__ __half  g_hist[(size_t)BATCH * K_PAD];           // 84 MB
__device__ __half  g_w2f[(size_t)128 * HIDDEN];             // 256 KB
__device__ __half  g_wcf[(size_t)128 * K_PAD];              // 2.6 MB
__device__ __half  g_part[(size_t)BATCH * NSLICE * PPITCH]; // 6.8 MB [b][sl][o]
__device__ __align__(16) float g_bc[OUTPUT];

// ---------------- PTX helpers (portable sm_80-class only) ----------------
__device__ __forceinline__ uint32_t smem_u32(const void* p) {
    uint32_t a;
    asm("{ .reg .u64 t; cvta.to.shared.u64 t, %1; cvt.u32.u64 %0, t; }"
        : "=r"(a) : "l"(p));
    return a;
}

__device__ __forceinline__ void cp16(uint32_t s, const void* g) {
    asm volatile("cp.async.cg.shared.global [%0], [%1], 16;" :: "r"(s), "l"(g));
}
__device__ __forceinline__ void cp16ca(uint32_t s, const void* g) {
    asm volatile("cp.async.ca.shared.global [%0], [%1], 16;" :: "r"(s), "l"(g));
}
#define CP_COMMIT() asm volatile("cp.async.commit_group;" ::: "memory")
#define CP_WAIT1()  asm volatile("cp.async.wait_group 1;"  ::: "memory")

__device__ __forceinline__ void ldsm4(uint32_t* r, uint32_t a) {
    asm volatile("ldmatrix.sync.aligned.m8n8.x4.shared.b16 {%0,%1,%2,%3}, [%4];"
        : "=r"(r[0]), "=r"(r[1]), "=r"(r[2]), "=r"(r[3]) : "r"(a));
}
__device__ __forceinline__ void ldsm4t(uint32_t* r, uint32_t a) {
    asm volatile("ldmatrix.sync.aligned.m8n8.x4.trans.shared.b16 {%0,%1,%2,%3}, [%4];"
        : "=r"(r[0]), "=r"(r[1]), "=r"(r[2]), "=r"(r[3]) : "r"(a));
}

// D(16x8,f32) += A(16x16,f16) @ B(16x8,f16)
__device__ __forceinline__ void mma_f16(float* c, const uint32_t* a, const uint32_t* b) {
    asm volatile(
        "mma.sync.aligned.m16n8k16.row.col.f32.f16.f16.f32 "
        "{%0,%1,%2,%3}, {%4,%5,%6,%7}, {%8,%9}, {%0,%1,%2,%3};"
        : "+f"(c[0]), "+f"(c[1]), "+f"(c[2]), "+f"(c[3])
        : "r"(a[0]), "r"(a[1]), "r"(a[2]), "r"(a[3]), "r"(b[0]), "r"(b[1]));
}

#define PA 144     // smem pitch (bytes) for 64-col 16-bit rows, +8 elem pad

// ---------------- kernel 1: prelude (hist + W2 conv + bc) ----------------
#define NB_HIST 4096
#define NB_W2   512
#define NB_BC   13
#define NB_TOTAL (NB_HIST + NB_W2 + NB_BC)

__global__ void __launch_bounds__(256) prelude_kernel(
        const int* __restrict__ words, const float* __restrict__ b1,
        const float* __restrict__ W2,  const float* __restrict__ b2) {
    __shared__ __align__(16) unsigned cnt[K_PAD / 2];
    const int bid = blockIdx.x, tid = threadIdx.x;

    if (bid < NB_HIST) {
        uint4 z = make_uint4(0u, 0u, 0u, 0u);
        uint4* cz = (uint4*)cnt;
        #pragma unroll
        for (int i = tid; i < K_PAD / 8; i += 256) cz[i] = z;
        __syncthreads();
        const int4* w4 = (const int4*)(words + (size_t)bid * MAXLEN);
        #pragma unroll
        for (int j = tid; j < MAXLEN / 4; j += 256) {     // 2 iters of int4
            int4 v = w4[j];
            unsigned c0 = (unsigned)v.x, c1 = (unsigned)v.y;
            unsigned c2 = (unsigned)v.z, c3 = (unsigned)v.w;
            atomicAdd(&cnt[c0 >> 1], 1u << ((c0 & 1u) * 16));
            atomicAdd(&cnt[c1 >> 1], 1u << ((c1 & 1u) * 16));
            atomicAdd(&cnt[c2 >> 1], 1u << ((c2 & 1u) * 16));
            atomicAdd(&cnt[c3 >> 1], 1u << ((c3 & 1u) * 16));
        }
        __syncthreads();
        uint4* out = (uint4*)(g_hist + (size_t)bid * K_PAD);
        #pragma unroll
        for (int i = tid; i < K_PAD / 8; i += 256) {
            unsigned c0 = cnt[4 * i], c1 = cnt[4 * i + 1];
            unsigned c2 = cnt[4 * i + 2], c3 = cnt[4 * i + 3];
            __half2 h0 = __floats2half2_rn((float)(c0 & 0xFFFFu), (float)(c0 >> 16));
            __half2 h1 = __floats2half2_rn((float)(c1 & 0xFFFFu), (float)(c1 >> 16));
            __half2 h2 = __floats2half2_rn((float)(c2 & 0xFFFFu), (float)(c2 >> 16));
            __half2 h3 = __floats2half2_rn((float)(c3 & 0xFFFFu), (float)(c3 >> 16));
            out[i] = make_uint4(*(uint32_t*)&h0, *(uint32_t*)&h1,
                                *(uint32_t*)&h2, *(uint32_t*)&h3);
        }
    } else if (bid < NB_HIST + NB_W2) {
        unsigned i = (bid - NB_HIST) * 256u + tid;           // over 128*1024
        unsigned o = i >> 10;
        float v = (o < OUTPUT) ? W2[(size_t)o * HIDDEN + (i & 1023u)] : 0.f;
        g_w2f[i] = __float2half_rn(v);
    } else {
        int o = (bid - NB_HIST - NB_W2) * 8 + (tid >> 5);
        if (o < OUTPUT) {
            int lane = tid & 31;
            const float* w = W2 + (size_t)o * HIDDEN;
            float s = 0.f;
            #pragma unroll 8
            for (int h = lane; h < HIDDEN; h += 32) s += w[h] * b1[h];
            #pragma unroll
            for (int off = 16; off; off >>= 1)
                s += __shfl_xor_sync(0xFFFFFFFFu, s, off);
            if (lane == 0) g_bc[o] = b2[o] + s;
        }
    }
}

// ---------------- kernel 2: Wc = W2 @ W1 (fused W1 fp32->fp16) -----------
// CTA 128 o x 64 c, K=1024 (16 chunks). grid 160. 8 warps (4m x 2n).
#define WC_A 0
#define WC_B 18432
#define WC_STG 27648

__global__ void __launch_bounds__(256, 2) wc_gemm(const float* __restrict__ W1) {
    extern __shared__ char smn[];
    uint32_t sb = smem_u32(smn);
    const int tid = threadIdx.x, lid = tid & 31, wid = tid >> 5;
    const int wm = wid >> 1, wn = wid & 1, gid = lid >> 2, t4 = lid & 3;
    const int c0 = blockIdx.x * 64;

    const int arow = tid >> 1;
    const int acol = (tid & 1) * 64;
    const char* gA = (const char*)(g_w2f + (size_t)arow * HIDDEN) + acol;
    const uint32_t sA = sb + WC_A + arow * PA + acol;

    const int brow = tid >> 2;
    const int bcole = (tid & 3) * 16;
    const uint32_t oB = WC_B + brow * PA + bcole * 2;

    float4 rb[4];
    auto loadB = [&](int it) {
        const float* p = W1 + (size_t)(it * 64 + brow) * CHARS + c0 + bcole;
        #pragma unroll
        for (int i = 0; i < 4; i++) {
            int c = c0 + bcole + i * 4;
            rb[i] = (c < CHARS) ? *(const float4*)(p + i * 4)
                                : make_float4(0.f, 0.f, 0.f, 0.f);
        }
    };
    auto stsB = [&](int slot) {
        uint32_t so = slot * WC_STG;
        #pragma unroll
        for (int j = 0; j < 2; j++) {
            __half2 h0 = __floats2half2_rn(rb[2*j].x,   rb[2*j].y);
            __half2 h1 = __floats2half2_rn(rb[2*j].z,   rb[2*j].w);
            __half2 h2 = __floats2half2_rn(rb[2*j+1].x, rb[2*j+1].y);
            __half2 h3 = __floats2half2_rn(rb[2*j+1].z, rb[2*j+1].w);
            *(uint4*)(smn + oB + so + j * 16) =
                make_uint4(*(uint32_t*)&h0, *(uint32_t*)&h1,
                           *(uint32_t*)&h2, *(uint32_t*)&h3);
        }
    };
    auto cpA = [&](int it, int slot) {
        if (it < NCHUNK_WC) {
            uint32_t so = slot * WC_STG;
            size_t ka = (size_t)it * 128;
            #pragma unroll
            for (int i = 0; i < 4; i++) cp16(sA + so + i * 16, gA + ka + i * 16);
        }
        CP_COMMIT();
    };

    float acc[2][4][4];
    #pragma unroll
    for (int mb = 0; mb < 2; mb++)
        #pragma unroll
        for (int nf = 0; nf < 4; nf++)
            #pragma unroll
            for (int e = 0; e < 4; e++) acc[mb][nf][e] = 0.f;

    loadB(0); stsB(0);
    loadB(1);
    cpA(0, 0); cpA(1, 1);

    int sc = 0, sn = 2;
    for (int it = 0; it < NCHUNK_WC; ++it) {
        uint32_t st = sb + sc * WC_STG;
        CP_WAIT1();
        __syncthreads();
        if (it + 1 < NCHUNK_WC) stsB((it + 1) % 3);
        if (it + 2 < NCHUNK_WC) loadB(it + 2);
        cpA(it + 2, sn);
        #pragma unroll
        for (int ks = 0; ks < 4; ks++) {
            uint32_t a[2][4];
            #pragma unroll
            for (int mb = 0; mb < 2; mb++) {
                uint32_t r = (wm * 32 + mb * 16 + (lid & 15));
                ldsm4(a[mb], st + WC_A + r * PA + ks * 32 + (lid >> 4) * 16);
            }
            #pragma unroll
            for (int nq = 0; nq < 2; nq++) {
                uint32_t r = ks * 16 + ((lid >> 3) & 1) * 8 + (lid & 7);
                uint32_t cb = (wn * 32 + nq * 16) * 2 + ((lid >> 4) & 1) * 16;
                uint32_t b[4];
                ldsm4t(b, st + WC_B + r * PA + cb);
                #pragma unroll
                for (int mb = 0; mb < 2; mb++)
                    #pragma unroll
                    for (int f = 0; f < 2; f++)
                        mma_f16(acc[mb][nq * 2 + f], a[mb], &b[f * 2]);
            }
        }
        sc = (sc == 2) ? 0 : sc + 1;
        sn = (sn == 2) ? 0 : sn + 1;
    }

    #pragma unroll
    for (int mb = 0; mb < 2; mb++)
        #pragma unroll
        for (int nf = 0; nf < 4; nf++) {
            int o = wm * 32 + mb * 16 + gid;
            int c = c0 + wn * 32 + nf * 8 + t4 * 2;
            *(__half2*)(g_wcf + (size_t)o * K_PAD + c) =
                __floats2half2_rn(acc[mb][nf][0], acc[mb][nf][1]);
            *(__half2*)(g_wcf + (size_t)(o + 8) * K_PAD + c) =
                __floats2half2_rn(acc[mb][nf][2], acc[mb][nf][3]);
        }
}

// ---------------- kernel 3: main GEMM  part = hist @ Wc^T (fp16) ---------
// CTA 128 m x 112 n (covers OUTPUT=100), 128 threads = 4 warps.
// wn=0 warps: 64x64; wn=1 warps: 64x48. 3 stages, 1 barrier/iter.
// Partials stored fp16 to [b][sl][PPITCH].
#define MG_A    0                      // 3 x 18432
#define MG_B    55296                  // 3 x 16128
#define B_STG   16128                  // 112 * 144
#define MG_SMEM (55296 + 3 * B_STG)    // 103680

__global__ void __launch_bounds__(128, 2) main_gemm() {
    extern __shared__ char smn[];
    uint32_t sb = smem_u32(smn);
    const int tid = threadIdx.x, lid = tid & 31, wid = tid >> 5;
    const int wm = wid >> 1, wn = wid & 1, gid = lid >> 2, t4 = lid & 3;
    const int m0 = blockIdx.x * 128;
    const int kbase = blockIdx.y * K_SLICE;
    const int nqmax = 4 - wn;

    const char* gA = (const char*)(g_hist + (size_t)(m0 + tid) * K_PAD + kbase);
    const uint32_t sA = sb + MG_A + tid * PA;
    const int rb8  = tid >> 3;
    const int bcol = (tid & 7) * 16;
    const char* gBc = (const char*)g_wcf + (size_t)kbase * 2 + bcol;
    const uint32_t sBb = sb + MG_B + bcol;

    auto issue = [&](int it, int s) {
        if (it < NCHUNK_MAIN) {
            size_t ko = (size_t)it * 128;
            uint32_t soA = s * 18432, soB = s * B_STG;
            #pragma unroll
            for (int i = 0; i < 8; i++)
                cp16(sA + soA + i * 16, gA + ko + i * 16);
            #pragma unroll
            for (int i = 0; i < 7; i++) {
                int row = i * 16 + rb8;
                cp16ca(sBb + soB + row * PA,
                       gBc + (size_t)row * (K_PAD * 2) + ko);
            }
        }
        CP_COMMIT();
    };

    float acc[4][8][4];
    #pragma unroll
    for (int mb = 0; mb < 4; mb++)
        #pragma unroll
        for (int nf = 0; nf < 8; nf++)
            #pragma unroll
            for (int e = 0; e < 4; e++) acc[mb][nf][e] = 0.f;

    const uint32_t aoff = (wm * 64 + (lid & 15)) * PA + (lid >> 4) * 16;
    const uint32_t boff = (wn * 64 + ((lid >> 4) & 1) * 8 + (lid & 7)) * PA
                          + ((lid >> 3) & 1) * 16;

    issue(0, 0); issue(1, 1);
    int sc = 0, sn = 2;
    for (int it = 0; it < NCHUNK_MAIN; ++it) {
        uint32_t stA = sb + MG_A + sc * 18432;
        uint32_t stB = sb + MG_B + sc * B_STG;
        CP_WAIT1();
        __syncthreads();
        issue(it + 2, sn);
        #pragma unroll
        for (int ks = 0; ks < 4; ks++) {
            uint32_t ko = ks * 32;
            uint32_t a[4][4], b[4][4];
            #pragma unroll
            for (int mb = 0; mb < 4; mb++)
                ldsm4(a[mb], stA + aoff + mb * 16 * PA + ko);
            #pragma unroll
            for (int nq = 0; nq < 4; nq++)
                if (nq < nqmax)
                    ldsm4(b[nq], stB + boff + nq * 16 * PA + ko);
            #pragma unroll
            for (int nq = 0; nq < 4; nq++)
                if (nq < nqmax)
                    #pragma unroll
                    for (int mb = 0; mb < 4; mb++)
                        #pragma unroll
                        for (int f = 0; f < 2; f++)
                            mma_f16(acc[mb][nq * 2 + f], a[mb], &b[nq][f * 2]);
        }
        sc = (sc == 2) ? 0 : sc + 1;
        sn = (sn == 2) ? 0 : sn + 1;
    }

    // epilogue: fp16 partials, layout [b][sl][PPITCH]
    #pragma unroll
    for (int mb = 0; mb < 4; mb++)
        #pragma unroll
        for (int nf = 0; nf < 8; nf++) {
            int r = m0 + wm * 64 + mb * 16 + gid;
            int c = wn * 64 + nf * 8 + t4 * 2;
            if (c < OUTPUT) {
                *(__half2*)(g_part + ((size_t)r * NSLICE + blockIdx.y) * PPITCH + c) =
                    __floats2half2_rn(acc[mb][nf][0], acc[mb][nf][1]);
                *(__half2*)(g_part + ((size_t)(r + 8) * NSLICE + blockIdx.y) * PPITCH + c) =
                    __floats2half2_rn(acc[mb][nf][2], acc[mb][nf][3]);
            }
        }
}

// ---------------- kernel 4: split-K reduce + bias (flat mapping) ---------
// thread i -> (b = i/25, quad = i%25); all 32 lanes active, coalesced reads.
__global__ void __launch_bounds__(256) reduce_kernel(float* __restrict__ out) {
    int i = blockIdx.x * 256 + threadIdx.x;       // over BATCH*25 = 102400
    int b = i / 25;
    int o = (i - b * 25) * 4;
    float4 s = *(const float4*)(g_bc + o);
    const __half* pb = g_part + (size_t)b * NSLICE * PPITCH + o;
    #pragma unroll
    for (int sl = 0; sl < NSLICE; sl++) {
        uint2 v = *(const uint2*)(pb + sl * PPITCH);
        float2 p0 = __half22float2(*(__half2*)&v.x);
        float2 p1 = __half22float2(*(__half2*)&v.y);
        s.x += p0.x; s.y += p0.y; s.z += p1.x; s.w += p1.y;
    }
    *(float4*)(out + (size_t)b * OUTPUT + o) = s;
}

// ---------------- launch ---------------------------------------------------
extern "C" void kernel_launch(void* const* d_in, const int* in_sizes, int n_in,
                              void* d_out, int out_size) {
    const int*   words = (const int*)  d_in[0];
    const float* W1    = (const float*)d_in[1];
    const float* b1    = (const float*)d_in[2];
    const float* W2    = (const float*)d_in[3];
    const float* b2    = (const float*)d_in[4];

    cudaFuncSetAttribute(wc_gemm,
        cudaFuncAttributeMaxDynamicSharedMemorySize, 3 * WC_STG);
    cudaFuncSetAttribute(main_gemm,
        cudaFuncAttributeMaxDynamicSharedMemorySize, MG_SMEM);

    prelude_kernel<<<NB_TOTAL, 256>>>(words, b1, W2, b2);
    wc_gemm<<<K_PAD / 64, 256, 3 * WC_STG>>>(W1);
    main_gemm<<<dim3(32, NSLICE), 128, MG_SMEM>>>();
    reduce_kernel<<<(BATCH * 25) / 256, 256>>>((float*)d_out);
}

// round 17
// speedup vs baseline: 1.1009x; 1.0565x over previous
#include <cuda_runtime.h>
#include <cuda_fp16.h>
#include <cstdint>

#define CHARS   10000
#define HIDDEN  1024
#define OUTPUT  100
#define BATCH   4096
#define MAXLEN  2048

#define K_PAD   10368                 // 64 * 162, divisible by 9*64
#define PPITCH  104                   // g_part row pitch (halfs)
#define NSLICE  9
#define K_SLICE (K_PAD / NSLICE)      // 1152
#define NCHUNK_MAIN (K_SLICE / 64)    // 18
#define NCHUNK_WC   (HIDDEN / 64)     // 16

// ---------------- device scratch (static; allocations are banned) --------
__device__ __half  g_hist[(size_t)BATCH * K_PAD];           // 85 MB
__device__ __half  g_w2f[(size_t)128 * HIDDEN];             // 256 KB
__device__ __half  g_wcf[(size_t)128 * K_PAD];              // 2.65 MB
__device__ __half  g_part[(size_t)BATCH * NSLICE * PPITCH]; // 7.7 MB [b][sl][o]
__device__ __align__(16) float g_bc[OUTPUT];

// ---------------- PTX helpers (portable sm_80-class only) ----------------
__device__ __forceinline__ uint32_t smem_u32(const void* p) {
    uint32_t a;
    asm("{ .reg .u64 t; cvta.to.shared.u64 t, %1; cvt.u32.u64 %0, t; }"
        : "=r"(a) : "l"(p));
    return a;
}

__device__ __forceinline__ void cp16(uint32_t s, const void* g) {
    asm volatile("cp.async.cg.shared.global [%0], [%1], 16;" :: "r"(s), "l"(g));
}
__device__ __forceinline__ void cp16ca(uint32_t s, const void* g) {
    asm volatile("cp.async.ca.shared.global [%0], [%1], 16;" :: "r"(s), "l"(g));
}
#define CP_COMMIT() asm volatile("cp.async.commit_group;" ::: "memory")
#define CP_WAIT0()  asm volatile("cp.async.wait_group 0;"  ::: "memory")
#define CP_WAIT1()  asm volatile("cp.async.wait_group 1;"  ::: "memory")

__device__ __forceinline__ void ldsm4(uint32_t* r, uint32_t a) {
    asm volatile("ldmatrix.sync.aligned.m8n8.x4.shared.b16 {%0,%1,%2,%3}, [%4];"
        : "=r"(r[0]), "=r"(r[1]), "=r"(r[2]), "=r"(r[3]) : "r"(a));
}
__device__ __forceinline__ void ldsm4t(uint32_t* r, uint32_t a) {
    asm volatile("ldmatrix.sync.aligned.m8n8.x4.trans.shared.b16 {%0,%1,%2,%3}, [%4];"
        : "=r"(r[0]), "=r"(r[1]), "=r"(r[2]), "=r"(r[3]) : "r"(a));
}

// D(16x8,f32) += A(16x16,f16) @ B(16x8,f16)
__device__ __forceinline__ void mma_f16(float* c, const uint32_t* a, const uint32_t* b) {
    asm volatile(
        "mma.sync.aligned.m16n8k16.row.col.f32.f16.f16.f32 "
        "{%0,%1,%2,%3}, {%4,%5,%6,%7}, {%8,%9}, {%0,%1,%2,%3};"
        : "+f"(c[0]), "+f"(c[1]), "+f"(c[2]), "+f"(c[3])
        : "r"(a[0]), "r"(a[1]), "r"(a[2]), "r"(a[3]), "r"(b[0]), "r"(b[1]));
}

#define PA 144     // smem pitch (bytes) for 64-col 16-bit rows, +8 elem pad

// ---------------- kernel 1: prelude (hist + W2 conv + bc) ----------------
#define NB_HIST 4096
#define NB_W2   512
#define NB_BC   13
#define NB_TOTAL (NB_HIST + NB_W2 + NB_BC)

__global__ void __launch_bounds__(256) prelude_kernel(
        const int* __restrict__ words, const float* __restrict__ b1,
        const float* __restrict__ W2,  const float* __restrict__ b2) {
    __shared__ __align__(16) unsigned cnt[K_PAD / 2];
    const int bid = blockIdx.x, tid = threadIdx.x;

    if (bid < NB_HIST) {
        uint4 z = make_uint4(0u, 0u, 0u, 0u);
        uint4* cz = (uint4*)cnt;
        for (int i = tid; i < K_PAD / 8; i += 256) cz[i] = z;
        __syncthreads();
        const int4* w4 = (const int4*)(words + (size_t)bid * MAXLEN);
        #pragma unroll
        for (int j = tid; j < MAXLEN / 4; j += 256) {
            int4 v = w4[j];
            unsigned c0 = (unsigned)v.x, c1 = (unsigned)v.y;
            unsigned c2 = (unsigned)v.z, c3 = (unsigned)v.w;
            atomicAdd(&cnt[c0 >> 1], 1u << ((c0 & 1u) * 16));
            atomicAdd(&cnt[c1 >> 1], 1u << ((c1 & 1u) * 16));
            atomicAdd(&cnt[c2 >> 1], 1u << ((c2 & 1u) * 16));
            atomicAdd(&cnt[c3 >> 1], 1u << ((c3 & 1u) * 16));
        }
        __syncthreads();
        uint4* out = (uint4*)(g_hist + (size_t)bid * K_PAD);
        for (int i = tid; i < K_PAD / 8; i += 256) {
            unsigned c0 = cnt[4 * i], c1 = cnt[4 * i + 1];
            unsigned c2 = cnt[4 * i + 2], c3 = cnt[4 * i + 3];
            __half2 h0 = __floats2half2_rn((float)(c0 & 0xFFFFu), (float)(c0 >> 16));
            __half2 h1 = __floats2half2_rn((float)(c1 & 0xFFFFu), (float)(c1 >> 16));
            __half2 h2 = __floats2half2_rn((float)(c2 & 0xFFFFu), (float)(c2 >> 16));
            __half2 h3 = __floats2half2_rn((float)(c3 & 0xFFFFu), (float)(c3 >> 16));
            out[i] = make_uint4(*(uint32_t*)&h0, *(uint32_t*)&h1,
                                *(uint32_t*)&h2, *(uint32_t*)&h3);
        }
    } else if (bid < NB_HIST + NB_W2) {
        unsigned i = (bid - NB_HIST) * 256u + tid;           // over 128*1024
        unsigned o = i >> 10;
        float v = (o < OUTPUT) ? W2[(size_t)o * HIDDEN + (i & 1023u)] : 0.f;
        g_w2f[i] = __float2half_rn(v);
    } else {
        int o = (bid - NB_HIST - NB_W2) * 8 + (tid >> 5);
        if (o < OUTPUT) {
            int lane = tid & 31;
            const float* w = W2 + (size_t)o * HIDDEN;
            float s = 0.f;
            #pragma unroll 8
            for (int h = lane; h < HIDDEN; h += 32) s += w[h] * b1[h];
            #pragma unroll
            for (int off = 16; off; off >>= 1)
                s += __shfl_xor_sync(0xFFFFFFFFu, s, off);
            if (lane == 0) g_bc[o] = b2[o] + s;
        }
    }
}

// ---------------- kernel 2: Wc = W2 @ W1 (fused W1 fp32->fp16) -----------
// CTA 128 o x 64 c, K=1024 (16 chunks). grid 162. 8 warps (4m x 2n).
#define WC_A 0
#define WC_B 18432
#define WC_STG 27648

__global__ void __launch_bounds__(256, 2) wc_gemm(const float* __restrict__ W1) {
    extern __shared__ char smn[];
    uint32_t sb = smem_u32(smn);
    const int tid = threadIdx.x, lid = tid & 31, wid = tid >> 5;
    const int wm = wid >> 1, wn = wid & 1, gid = lid >> 2, t4 = lid & 3;
    const int c0 = blockIdx.x * 64;

    const int arow = tid >> 1;
    const int acol = (tid & 1) * 64;
    const char* gA = (const char*)(g_w2f + (size_t)arow * HIDDEN) + acol;
    const uint32_t sA = sb + WC_A + arow * PA + acol;

    const int brow = tid >> 2;
    const int bcole = (tid & 3) * 16;
    const uint32_t oB = WC_B + brow * PA + bcole * 2;

    float4 rb[4];
    auto loadB = [&](int it) {
        const float* p = W1 + (size_t)(it * 64 + brow) * CHARS + c0 + bcole;
        #pragma unroll
        for (int i = 0; i < 4; i++) {
            int c = c0 + bcole + i * 4;
            rb[i] = (c < CHARS) ? *(const float4*)(p + i * 4)
                                : make_float4(0.f, 0.f, 0.f, 0.f);
        }
    };
    auto stsB = [&](int slot) {
        uint32_t so = slot * WC_STG;
        #pragma unroll
        for (int j = 0; j < 2; j++) {
            __half2 h0 = __floats2half2_rn(rb[2*j].x,   rb[2*j].y);
            __half2 h1 = __floats2half2_rn(rb[2*j].z,   rb[2*j].w);
            __half2 h2 = __floats2half2_rn(rb[2*j+1].x, rb[2*j+1].y);
            __half2 h3 = __floats2half2_rn(rb[2*j+1].z, rb[2*j+1].w);
            *(uint4*)(smn + oB + so + j * 16) =
                make_uint4(*(uint32_t*)&h0, *(uint32_t*)&h1,
                           *(uint32_t*)&h2, *(uint32_t*)&h3);
        }
    };
    auto cpA = [&](int it, int slot) {
        if (it < NCHUNK_WC) {
            uint32_t so = slot * WC_STG;
            size_t ka = (size_t)it * 128;
            #pragma unroll
            for (int i = 0; i < 4; i++) cp16(sA + so + i * 16, gA + ka + i * 16);
        }
        CP_COMMIT();
    };

    float acc[2][4][4];
    #pragma unroll
    for (int mb = 0; mb < 2; mb++)
        #pragma unroll
        for (int nf = 0; nf < 4; nf++)
            #pragma unroll
            for (int e = 0; e < 4; e++) acc[mb][nf][e] = 0.f;

    loadB(0); stsB(0);
    loadB(1);
    cpA(0, 0); cpA(1, 1);

    int sc = 0, sn = 2;
    for (int it = 0; it < NCHUNK_WC; ++it) {
        uint32_t st = sb + sc * WC_STG;
        CP_WAIT1();
        __syncthreads();
        if (it + 1 < NCHUNK_WC) stsB((it + 1) % 3);
        if (it + 2 < NCHUNK_WC) loadB(it + 2);
        cpA(it + 2, sn);
        #pragma unroll
        for (int ks = 0; ks < 4; ks++) {
            uint32_t a[2][4];
            #pragma unroll
            for (int mb = 0; mb < 2; mb++) {
                uint32_t r = (wm * 32 + mb * 16 + (lid & 15));
                ldsm4(a[mb], st + WC_A + r * PA + ks * 32 + (lid >> 4) * 16);
            }
            #pragma unroll
            for (int nq = 0; nq < 2; nq++) {
                uint32_t r = ks * 16 + ((lid >> 3) & 1) * 8 + (lid & 7);
                uint32_t cb = (wn * 32 + nq * 16) * 2 + ((lid >> 4) & 1) * 16;
                uint32_t b[4];
                ldsm4t(b, st + WC_B + r * PA + cb);
                #pragma unroll
                for (int mb = 0; mb < 2; mb++)
                    #pragma unroll
                    for (int f = 0; f < 2; f++)
                        mma_f16(acc[mb][nq * 2 + f], a[mb], &b[f * 2]);
            }
        }
        sc = (sc == 2) ? 0 : sc + 1;
        sn = (sn == 2) ? 0 : sn + 1;
    }

    #pragma unroll
    for (int mb = 0; mb < 2; mb++)
        #pragma unroll
        for (int nf = 0; nf < 4; nf++) {
            int o = wm * 32 + mb * 16 + gid;
            int c = c0 + wn * 32 + nf * 8 + t4 * 2;
            *(__half2*)(g_wcf + (size_t)o * K_PAD + c) =
                __floats2half2_rn(acc[mb][nf][0], acc[mb][nf][1]);
            *(__half2*)(g_wcf + (size_t)(o + 8) * K_PAD + c) =
                __floats2half2_rn(acc[mb][nf][2], acc[mb][nf][3]);
        }
}

// ---------------- kernel 3: main GEMM  part = hist @ Wc^T (fp16) ---------
// CTA 64 m x 112 n, 128 threads = 4 warps (2m x 2n), warp tile 32x56.
// 2 smem stages, 1 barrier/iter, 4 CTAs/SM -> 16 warps/SM (latency fix).
#define A_BYTES 9216                   // 64 * 144
#define B_BYTES 16128                  // 112 * 144
#define MG_STG  (A_BYTES + B_BYTES)    // 25344
#define MG_SMEM (2 * MG_STG)           // 50688

__global__ void __launch_bounds__(128, 4) main_gemm() {
    extern __shared__ char smn[];
    uint32_t sb = smem_u32(smn);
    const int tid = threadIdx.x, lid = tid & 31, wid = tid >> 5;
    const int wm = wid >> 1, wn = wid & 1, gid = lid >> 2, t4 = lid & 3;
    const int m0 = blockIdx.x * 64;
    const int kbase = blockIdx.y * K_SLICE;
    const int nqmax = 4 - wn;          // wn0: n[0:64), wn1: n[64:112)

    // A cp.async: 64 rows x 128B -> 2 threads/row, 4 cp16 each
    const int arow = tid >> 1;
    const int ahalf = (tid & 1) * 64;
    const char* gA = (const char*)(g_hist + (size_t)(m0 + arow) * K_PAD + kbase) + ahalf;
    const uint32_t sA = sb + arow * PA + ahalf;
    // B cp.async: 112 rows x 128B = 896 cp16 -> 7 per thread
    const int rb8  = tid >> 3;
    const int bcol = (tid & 7) * 16;
    const char* gBc = (const char*)g_wcf + (size_t)kbase * 2 + bcol;
    const uint32_t sBb = sb + A_BYTES + bcol;

    auto issue = [&](int it, int s) {
        if (it < NCHUNK_MAIN) {
            size_t ko = (size_t)it * 128;
            uint32_t so = s * MG_STG;
            #pragma unroll
            for (int i = 0; i < 4; i++)
                cp16(sA + so + i * 16, gA + ko + i * 16);
            #pragma unroll
            for (int i = 0; i < 7; i++) {
                int row = i * 16 + rb8;
                cp16ca(sBb + so + row * PA,
                       gBc + (size_t)row * (K_PAD * 2) + ko);
            }
        }
        CP_COMMIT();
    };

    float acc[2][8][4];
    #pragma unroll
    for (int mb = 0; mb < 2; mb++)
        #pragma unroll
        for (int nf = 0; nf < 8; nf++)
            #pragma unroll
            for (int e = 0; e < 4; e++) acc[mb][nf][e] = 0.f;

    const uint32_t aoff = (wm * 32 + (lid & 15)) * PA + (lid >> 4) * 16;
    const uint32_t boff = A_BYTES
                          + (wn * 64 + ((lid >> 4) & 1) * 8 + (lid & 7)) * PA
                          + ((lid >> 3) & 1) * 16;

    issue(0, 0);
    for (int it = 0; it < NCHUNK_MAIN; ++it) {
        uint32_t st = sb + (it & 1) * MG_STG;
        CP_WAIT0();                    // chunk it landed (only group in flight)
        __syncthreads();               // + all warps done reading slot (it+1)&1
        issue(it + 1, (it + 1) & 1);   // overlap next load with this compute
        #pragma unroll
        for (int ks = 0; ks < 4; ks++) {
            uint32_t ko = ks * 32;
            uint32_t a[2][4], b[4][4];
            #pragma unroll
            for (int mb = 0; mb < 2; mb++)
                ldsm4(a[mb], st + aoff + mb * 16 * PA + ko);
            #pragma unroll
            for (int nq = 0; nq < 4; nq++)
                if (nq < nqmax)
                    ldsm4(b[nq], st + boff + nq * 16 * PA + ko);
            #pragma unroll
            for (int nq = 0; nq < 4; nq++)
                if (nq < nqmax)
                    #pragma unroll
                    for (int mb = 0; mb < 2; mb++)
                        #pragma unroll
                        for (int f = 0; f < 2; f++)
                            mma_f16(acc[mb][nq * 2 + f], a[mb], &b[nq][f * 2]);
        }
    }

    // epilogue: fp16 partials, layout [b][sl][PPITCH]
    #pragma unroll
    for (int mb = 0; mb < 2; mb++)
        #pragma unroll
        for (int nf = 0; nf < 8; nf++) {
            int r = m0 + wm * 32 + mb * 16 + gid;
            int c = wn * 64 + nf * 8 + t4 * 2;
            if (c < OUTPUT) {
                *(__half2*)(g_part + ((size_t)r * NSLICE + blockIdx.y) * PPITCH + c) =
                    __floats2half2_rn(acc[mb][nf][0], acc[mb][nf][1]);
                *(__half2*)(g_part + ((size_t)(r + 8) * NSLICE + blockIdx.y) * PPITCH + c) =
                    __floats2half2_rn(acc[mb][nf][2], acc[mb][nf][3]);
            }
        }
}

// ---------------- kernel 4: split-K reduce + bias (flat mapping) ---------
__global__ void __launch_bounds__(256) reduce_kernel(float* __restrict__ out) {
    int i = blockIdx.x * 256 + threadIdx.x;       // over BATCH*25 = 102400
    int b = i / 25;
    int o = (i - b * 25) * 4;
    float4 s = *(const float4*)(g_bc + o);
    const __half* pb = g_part + (size_t)b * NSLICE * PPITCH + o;
    #pragma unroll
    for (int sl = 0; sl < NSLICE; sl++) {
        uint2 v = *(const uint2*)(pb + sl * PPITCH);
        float2 p0 = __half22float2(*(__half2*)&v.x);
        float2 p1 = __half22float2(*(__half2*)&v.y);
        s.x += p0.x; s.y += p0.y; s.z += p1.x; s.w += p1.y;
    }
    *(float4*)(out + (size_t)b * OUTPUT + o) = s;
}

// ---------------- launch ---------------------------------------------------
extern "C" void kernel_launch(void* const* d_in, const int* in_sizes, int n_in,
                              void* d_out, int out_size) {
    const int*   words = (const int*)  d_in[0];
    const float* W1    = (const float*)d_in[1];
    const float* b1    = (const float*)d_in[2];
    const float* W2    = (const float*)d_in[3];
    const float* b2    = (const float*)d_in[4];

    cudaFuncSetAttribute(wc_gemm,
        cudaFuncAttributeMaxDynamicSharedMemorySize, 3 * WC_STG);
    cudaFuncSetAttribute(main_gemm,
        cudaFuncAttributeMaxDynamicSharedMemorySize, MG_SMEM);

    prelude_kernel<<<NB_TOTAL, 256>>>(words, b1, W2, b2);
    wc_gemm<<<K_PAD / 64, 256, 3 * WC_STG>>>(W1);
    main_gemm<<<dim3(BATCH / 64, NSLICE), 128, MG_SMEM>>>();
    reduce_kernel<<<(BATCH * 25) / 256, 256>>>((float*)d_out);
}